// round 1
// baseline (speedup 1.0000x reference)
#include <cuda_runtime.h>
#include <mma.h>
#include <cstdint>

using namespace nvcuda;

// Shapes (fixed for this problem)
//  B=4, P=2048 -> T=8192 tokens, D=1024, H=16, KV=8, HD=64, F=4096, E=16, FE=256
#define T_TOK 8192
#define NPOS  2048

// ---------------- scratch (device globals; no allocation allowed) ----------------
__device__ float sc_h [8192*1024];   // rmsnorm output (h, then h2)
__device__ float sc_q [8192*1024];
__device__ float sc_k [8192*512];
__device__ float sc_v [8192*512];
__device__ float sc_ao[8192*1024];   // attention output
__device__ float sc_g [8192*4096];   // gate / activation
__device__ float sc_u [8192*4096];   // up
__device__ float sc_cos[2048*32];
__device__ float sc_sin[2048*32];

// ---------------- rmsnorm ----------------
__global__ __launch_bounds__(256)
void rmsnorm_kernel(const float* __restrict__ x, const float* __restrict__ w,
                    float* __restrict__ out)
{
    int t = blockIdx.x;
    const float* xr = x + (size_t)t * 1024;
    float* orow = out + (size_t)t * 1024;
    int tid = threadIdx.x;

    float4 v = *(const float4*)(xr + tid * 4);
    float s = v.x*v.x + v.y*v.y + v.z*v.z + v.w*v.w;
    #pragma unroll
    for (int o = 16; o; o >>= 1) s += __shfl_xor_sync(0xffffffffu, s, o);
    __shared__ float ws[8];
    if ((tid & 31) == 0) ws[tid >> 5] = s;
    __syncthreads();
    if (tid < 8) {
        float t2 = ws[tid];
        #pragma unroll
        for (int o = 4; o; o >>= 1) t2 += __shfl_xor_sync(0xffu, t2, o);
        if (tid == 0) ws[0] = t2;
    }
    __syncthreads();
    float rinv = rsqrtf(ws[0] * (1.0f / 1024.0f) + 1e-6f);
    float4 wv = *(const float4*)(w + tid * 4);
    float4 r;
    r.x = v.x * rinv * wv.x;
    r.y = v.y * rinv * wv.y;
    r.z = v.z * rinv * wv.z;
    r.w = v.w * rinv * wv.w;
    *(float4*)(orow + tid * 4) = r;
}

// ---------------- generic TF32 GEMM: C[M,N] = A[M,K] @ B[K,N] (+epilogues) -------
// Blocked-B addressing: addr(k,n) = B + (n/nbs)*nstride + k*ldb + (n%nbs)
// (normal matrices: nbs = 1<<28, nstride = 0, ldb = N)
__global__ __launch_bounds__(256)
void gemm_tf32(const float* __restrict__ A, const float* __restrict__ B,
               float* __restrict__ C, int M, int N, int K,
               int ldb, int nbs, long long nstride,
               const float* __restrict__ bias, const float* __restrict__ res,
               int accum)
{
    __shared__ float As[128 * 16];
    __shared__ float Bs[16 * 128];
    int bm = blockIdx.y * 128, bn = blockIdx.x * 128;
    int tid = threadIdx.x, wid = tid >> 5, lane = tid & 31;
    int wm = (wid >> 1) * 32, wn = (wid & 1) * 64;

    wmma::fragment<wmma::accumulator, 16, 16, 8, float> acc[2][4];
    #pragma unroll
    for (int i = 0; i < 2; i++)
        #pragma unroll
        for (int j = 0; j < 4; j++) wmma::fill_fragment(acc[i][j], 0.0f);

    for (int k0 = 0; k0 < K; k0 += 16) {
        #pragma unroll
        for (int it = 0; it < 2; it++) {
            int i = tid + it * 256;            // 0..511
            int r = i >> 2, c4 = i & 3;        // A: 128 rows x 4 float4
            float4 av = *(const float4*)(A + (size_t)(bm + r) * K + k0 + c4 * 4);
            *(float4*)(As + r * 16 + c4 * 4) = av;
        }
        #pragma unroll
        for (int it = 0; it < 2; it++) {
            int i = tid + it * 256;
            int r = i >> 5, c4 = i & 31;       // B: 16 rows x 32 float4
            int n = bn + c4 * 4;
            const float* bp = B + (size_t)(n / nbs) * nstride
                                + (size_t)(k0 + r) * ldb + (n % nbs);
            *(float4*)(Bs + r * 128 + c4 * 4) = *(const float4*)bp;
        }
        __syncthreads();
        #pragma unroll
        for (int kk = 0; kk < 16; kk += 8) {
            wmma::fragment<wmma::matrix_a, 16, 16, 8, wmma::precision::tf32, wmma::row_major> af[2];
            wmma::fragment<wmma::matrix_b, 16, 16, 8, wmma::precision::tf32, wmma::row_major> bf[4];
            #pragma unroll
            for (int i = 0; i < 2; i++) {
                wmma::load_matrix_sync(af[i], As + (wm + i * 16) * 16 + kk, 16);
                #pragma unroll
                for (int e = 0; e < af[i].num_elements; e++)
                    af[i].x[e] = wmma::__float_to_tf32(af[i].x[e]);
            }
            #pragma unroll
            for (int j = 0; j < 4; j++) {
                wmma::load_matrix_sync(bf[j], Bs + kk * 128 + wn + j * 16, 128);
                #pragma unroll
                for (int e = 0; e < bf[j].num_elements; e++)
                    bf[j].x[e] = wmma::__float_to_tf32(bf[j].x[e]);
            }
            #pragma unroll
            for (int i = 0; i < 2; i++)
                #pragma unroll
                for (int j = 0; j < 4; j++)
                    wmma::mma_sync(acc[i][j], af[i], bf[j], acc[i][j]);
        }
        __syncthreads();
    }

    // epilogue: stage each 16x16 frag through smem, apply bias/res/accum
    float* buf = As + wid * 256;
    #pragma unroll
    for (int i = 0; i < 2; i++)
        for (int j = 0; j < 4; j++) {
            wmma::store_matrix_sync(buf, acc[i][j], 16, wmma::mem_row_major);
            __syncwarp();
            int r0 = bm + wm + i * 16, c0 = bn + wn + j * 16;
            #pragma unroll
            for (int t2 = 0; t2 < 8; t2++) {
                int e = lane * 8 + t2;
                int er = e >> 4, ec = e & 15;
                float vv = buf[e];
                if (bias) vv += bias[c0 + ec];
                size_t ci = (size_t)(r0 + er) * N + (c0 + ec);
                if (res)   vv += res[ci];
                if (accum) vv += C[ci];
                C[ci] = vv;
            }
            __syncwarp();
        }
}

// ---------------- RoPE ----------------
__global__ void rope_table(float* __restrict__ ct, float* __restrict__ st)
{
    int i = blockIdx.x * 256 + threadIdx.x;   // 2048*32 = 65536
    int p = i >> 5, j = i & 31;
    float inv = powf(10000.0f, -(float)j * (1.0f / 32.0f));
    float ang = (float)p * inv;
    float s, c;
    sincosf(ang, &s, &c);
    ct[i] = c; st[i] = s;
}

__global__ void rope_apply(float* __restrict__ v, int nh,
                           const float* __restrict__ ct, const float* __restrict__ st)
{
    int i = blockIdx.x * 256 + threadIdx.x;
    int tot = T_TOK * nh * 32;
    if (i >= tot) return;
    int j = i & 31;
    int h = (i >> 5) % nh;
    int t = i / (nh * 32);
    int p = t & (NPOS - 1);
    float c = ct[p * 32 + j], s = st[p * 32 + j];
    size_t base = (size_t)t * nh * 64 + h * 64;
    float v1 = v[base + j], v2 = v[base + 32 + j];
    v[base + j]      = v1 * c - v2 * s;
    v[base + 32 + j] = v2 * c + v1 * s;
}

// ---------------- flash attention (causal, GQA 2:1, HD=64) ----------------
#define FLD 72
__global__ __launch_bounds__(256)
void flash_attn(const float* __restrict__ q, const float* __restrict__ k,
                const float* __restrict__ v, float* __restrict__ o)
{
    extern __shared__ float sm[];
    float* Qs = sm;                    // 64 x FLD (pre-scaled by 1/8)
    float* Ks = Qs + 64 * FLD;         // K tile; reused as P@V staging
    float* Vs = Ks + 64 * FLD;
    float* Ss = Vs + 64 * FLD;         // scores, then P
    float* Os = Ss + 64 * FLD;         // output accumulator
    float* mrow = Os + 64 * FLD;       // 64
    float* lrow = mrow + 64;           // 64
    float* crow = lrow + 64;           // 64

    int qt = blockIdx.x, h = blockIdx.y, b = blockIdx.z;
    int tid = threadIdx.x, wid = tid >> 5;
    int kvh = h >> 1;

    const float* qb = q + ((size_t)(b * NPOS + qt * 64)) * 1024 + h * 64;
    for (int i = tid; i < 1024; i += 256) {
        int r = i >> 4, c4 = i & 15;
        float4 val = *(const float4*)(qb + (size_t)r * 1024 + c4 * 4);
        val.x *= 0.125f; val.y *= 0.125f; val.z *= 0.125f; val.w *= 0.125f;
        *(float4*)(Qs + r * FLD + c4 * 4) = val;
    }
    for (int i = tid; i < 4096; i += 256) {
        int r = i >> 6, c = i & 63;
        Os[r * FLD + c] = 0.0f;
    }
    if (tid < 64) { mrow[tid] = -1e30f; lrow[tid] = 0.0f; }
    __syncthreads();

    int wm = (wid >> 1) * 16, wn = (wid & 1) * 32;

    for (int kt = 0; kt <= qt; kt++) {
        const float* kb = k + ((size_t)(b * NPOS + kt * 64)) * 512 + kvh * 64;
        const float* vb = v + ((size_t)(b * NPOS + kt * 64)) * 512 + kvh * 64;
        for (int i = tid; i < 1024; i += 256) {
            int r = i >> 4, c4 = i & 15;
            *(float4*)(Ks + r * FLD + c4 * 4) = *(const float4*)(kb + (size_t)r * 512 + c4 * 4);
            *(float4*)(Vs + r * FLD + c4 * 4) = *(const float4*)(vb + (size_t)r * 512 + c4 * 4);
        }
        __syncthreads();

        { // S = Qs @ Ks^T
            wmma::fragment<wmma::accumulator, 16, 16, 8, float> sacc[2];
            wmma::fill_fragment(sacc[0], 0.0f);
            wmma::fill_fragment(sacc[1], 0.0f);
            for (int d = 0; d < 64; d += 8) {
                wmma::fragment<wmma::matrix_a, 16, 16, 8, wmma::precision::tf32, wmma::row_major> af;
                wmma::load_matrix_sync(af, Qs + wm * FLD + d, FLD);
                #pragma unroll
                for (int e = 0; e < af.num_elements; e++) af.x[e] = wmma::__float_to_tf32(af.x[e]);
                #pragma unroll
                for (int j = 0; j < 2; j++) {
                    wmma::fragment<wmma::matrix_b, 16, 16, 8, wmma::precision::tf32, wmma::col_major> bf;
                    wmma::load_matrix_sync(bf, Ks + (wn + j * 16) * FLD + d, FLD);
                    #pragma unroll
                    for (int e = 0; e < bf.num_elements; e++) bf.x[e] = wmma::__float_to_tf32(bf.x[e]);
                    wmma::mma_sync(sacc[j], af, bf, sacc[j]);
                }
            }
            wmma::store_matrix_sync(Ss + wm * FLD + wn,      sacc[0], FLD, wmma::mem_row_major);
            wmma::store_matrix_sync(Ss + wm * FLD + wn + 16, sacc[1], FLD, wmma::mem_row_major);
        }
        __syncthreads();

        { // online softmax (4 threads per row)
            int r = tid >> 2, pp = tid & 3;
            int qg = qt * 64 + r;
            float vals[16]; float mx = -1e30f;
            #pragma unroll
            for (int c = 0; c < 16; c++) {
                int col = pp * 16 + c;
                float sv = Ss[r * FLD + col];
                if (kt * 64 + col > qg) sv = -1e30f;
                vals[c] = sv; mx = fmaxf(mx, sv);
            }
            mx = fmaxf(mx, __shfl_xor_sync(0xffffffffu, mx, 1));
            mx = fmaxf(mx, __shfl_xor_sync(0xffffffffu, mx, 2));
            float mold = mrow[r];
            float mnew = fmaxf(mold, mx);
            float sum = 0.0f;
            #pragma unroll
            for (int c = 0; c < 16; c++) {
                float e = __expf(vals[c] - mnew);
                Ss[r * FLD + pp * 16 + c] = e;
                sum += e;
            }
            sum += __shfl_xor_sync(0xffffffffu, sum, 1);
            sum += __shfl_xor_sync(0xffffffffu, sum, 2);
            if (pp == 0) {
                float cc = __expf(mold - mnew);
                lrow[r] = lrow[r] * cc + sum;
                mrow[r] = mnew;
                crow[r] = cc;
            }
        }
        __syncthreads();

        { // PV = Ss @ Vs -> stage into Ks
            wmma::fragment<wmma::accumulator, 16, 16, 8, float> pv[2];
            wmma::fill_fragment(pv[0], 0.0f);
            wmma::fill_fragment(pv[1], 0.0f);
            for (int kk = 0; kk < 64; kk += 8) {
                wmma::fragment<wmma::matrix_a, 16, 16, 8, wmma::precision::tf32, wmma::row_major> af;
                wmma::load_matrix_sync(af, Ss + wm * FLD + kk, FLD);
                #pragma unroll
                for (int e = 0; e < af.num_elements; e++) af.x[e] = wmma::__float_to_tf32(af.x[e]);
                #pragma unroll
                for (int j = 0; j < 2; j++) {
                    wmma::fragment<wmma::matrix_b, 16, 16, 8, wmma::precision::tf32, wmma::row_major> bf;
                    wmma::load_matrix_sync(bf, Vs + kk * FLD + wn + j * 16, FLD);
                    #pragma unroll
                    for (int e = 0; e < bf.num_elements; e++) bf.x[e] = wmma::__float_to_tf32(bf.x[e]);
                    wmma::mma_sync(pv[j], af, bf, pv[j]);
                }
            }
            wmma::store_matrix_sync(Ks + wm * FLD + wn,      pv[0], FLD, wmma::mem_row_major);
            wmma::store_matrix_sync(Ks + wm * FLD + wn + 16, pv[1], FLD, wmma::mem_row_major);
        }
        __syncthreads();

        for (int i = tid; i < 4096; i += 256) {
            int r = i >> 6, c = i & 63;
            Os[r * FLD + c] = Os[r * FLD + c] * crow[r] + Ks[r * FLD + c];
        }
        __syncthreads();
    }

    float* ob = o + ((size_t)(b * NPOS + qt * 64)) * 1024 + h * 64;
    for (int i = tid; i < 4096; i += 256) {
        int r = i >> 6, c = i & 63;
        ob[(size_t)r * 1024 + c] = Os[r * FLD + c] / lrow[r];
    }
}

// ---------------- SwiGLU (+optional expert-mask fold) ----------------
__global__ void swiglu_kernel(float* __restrict__ g, const float* __restrict__ u,
                              const float* __restrict__ mask)
{
    size_t i = (size_t)blockIdx.x * 256 + threadIdx.x;  // T*4096 total, exact
    float gv = g[i], uv = u[i];
    float a = gv / (1.0f + __expf(-gv)) * uv;
    if (mask) {
        size_t t = i >> 12;
        int e = (int)((i >> 8) & 15);
        a *= mask[t * 16 + e];
    }
    g[i] = a;
}

// ---------------- launch ----------------
extern "C" void kernel_launch(void* const* d_in, const int* in_sizes, int n_in,
                              void* d_out, int out_size)
{
    const float* x       = (const float*)d_in[0];
    const float* emask   = (const float*)d_in[1];
    const float* ln1     = (const float*)d_in[2];
    const float* wq      = (const float*)d_in[3];
    const float* bq      = (const float*)d_in[4];
    const float* wk      = (const float*)d_in[5];
    const float* bk      = (const float*)d_in[6];
    const float* wv      = (const float*)d_in[7];
    const float* bv      = (const float*)d_in[8];
    const float* wo      = (const float*)d_in[9];
    const float* ln2     = (const float*)d_in[10];
    const float* w_gate  = (const float*)d_in[11];
    const float* w_up    = (const float*)d_in[12];
    const float* w_down  = (const float*)d_in[13];
    const float* we_gate = (const float*)d_in[14];
    const float* we_up   = (const float*)d_in[15];
    const float* we_down = (const float*)d_in[16];
    float* out = (float*)d_out;

    float *h, *qb, *kb, *vb, *ao, *g, *u, *ct, *st;
    cudaGetSymbolAddress((void**)&h,  sc_h);
    cudaGetSymbolAddress((void**)&qb, sc_q);
    cudaGetSymbolAddress((void**)&kb, sc_k);
    cudaGetSymbolAddress((void**)&vb, sc_v);
    cudaGetSymbolAddress((void**)&ao, sc_ao);
    cudaGetSymbolAddress((void**)&g,  sc_g);
    cudaGetSymbolAddress((void**)&u,  sc_u);
    cudaGetSymbolAddress((void**)&ct, sc_cos);
    cudaGetSymbolAddress((void**)&st, sc_sin);

    const int FLASH_SMEM = (5 * 64 * FLD + 3 * 64) * 4;  // 92928 B
    cudaFuncSetAttribute(flash_attn, cudaFuncAttributeMaxDynamicSharedMemorySize, FLASH_SMEM);

    const int M = T_TOK;
    const int NB = 1 << 28;  // "no blocking" sentinel
    dim3 thr(256);

    // h = rmsnorm(x, ln1)
    rmsnorm_kernel<<<M, 256>>>(x, ln1, h);

    // q/k/v projections (+bias)
    gemm_tf32<<<dim3(8, 64), thr>>>(h, wq, qb, M, 1024, 1024, 1024, NB, 0, bq, nullptr, 0);
    gemm_tf32<<<dim3(4, 64), thr>>>(h, wk, kb, M,  512, 1024,  512, NB, 0, bk, nullptr, 0);
    gemm_tf32<<<dim3(4, 64), thr>>>(h, wv, vb, M,  512, 1024,  512, NB, 0, bv, nullptr, 0);

    // RoPE
    rope_table<<<256, 256>>>(ct, st);
    rope_apply<<<16384, 256>>>(qb, 16, ct, st);
    rope_apply<<< 8192, 256>>>(kb,  8, ct, st);

    // causal flash attention (GQA)
    flash_attn<<<dim3(32, 16, 4), 256, FLASH_SMEM>>>(qb, kb, vb, ao);

    // out = x + attn @ wo
    gemm_tf32<<<dim3(8, 64), thr>>>(ao, wo, out, M, 1024, 1024, 1024, NB, 0, nullptr, x, 0);

    // h2 = rmsnorm(out, ln2)
    rmsnorm_kernel<<<M, 256>>>(out, ln2, h);

    // dense MLP: out += (silu(h2@Wg) * (h2@Wu)) @ Wd
    gemm_tf32<<<dim3(32, 64), thr>>>(h, w_gate, g, M, 4096, 1024, 4096, NB, 0, nullptr, nullptr, 0);
    gemm_tf32<<<dim3(32, 64), thr>>>(h, w_up,   u, M, 4096, 1024, 4096, NB, 0, nullptr, nullptr, 0);
    swiglu_kernel<<<131072, 256>>>(g, u, nullptr);
    gemm_tf32<<<dim3(8, 64), thr>>>(g, w_down, out, M, 1024, 4096, 1024, NB, 0, nullptr, nullptr, 1);

    // routed experts: blocked-B gate/up (16 x (1024,256) blocks), mask folded
    // into activation, down-proj as one contiguous (4096,1024) GEMM.
    gemm_tf32<<<dim3(32, 64), thr>>>(h, we_gate, g, M, 4096, 1024, 256, 256, 1024LL * 256, nullptr, nullptr, 0);
    gemm_tf32<<<dim3(32, 64), thr>>>(h, we_up,   u, M, 4096, 1024, 256, 256, 1024LL * 256, nullptr, nullptr, 0);
    swiglu_kernel<<<131072, 256>>>(g, u, emask);
    gemm_tf32<<<dim3(8, 64), thr>>>(g, we_down, out, M, 1024, 4096, 1024, NB, 0, nullptr, nullptr, 1);
}